// round 1
// baseline (speedup 1.0000x reference)
#include <cuda_runtime.h>

#define TDIM   8
#define NTOK   8192      // B*S = 4*2048
#define DLAT   1024
#define DSYM   256
#define NCODE  512

// ---------------- scratch (static device globals; no runtime allocation) ----
static __device__ int   g_top[NTOK];
static __device__ int   g_used[TDIM];
static __device__ float g_zread[NTOK * DLAT];     // 32 MB
static __device__ float g_raw[NTOK * DSYM];       //  8 MB
static __device__ float g_scores[NTOK * NCODE];   // 16 MB
static __device__ float g_h[NTOK * DLAT];         // 32 MB
static __device__ float g_cbn[NCODE];

// ---------------- small kernels --------------------------------------------
__global__ void k_init_used() {
    if (threadIdx.x < TDIM) g_used[threadIdx.x] = 0;
}

// one warp per token: relevance[t] = dot(syms[t][n], Wq); argmax over t
__global__ void k_topidx(const float* __restrict__ syms,
                         const float* __restrict__ Wq) {
    int warp = (blockIdx.x * blockDim.x + threadIdx.x) >> 5;
    int lane = threadIdx.x & 31;
    if (warp >= NTOK) return;
    float wq[8];
#pragma unroll
    for (int i = 0; i < 8; i++) wq[i] = Wq[lane + 32 * i];
    float best = -3.0e38f;
    int bt = 0;
    for (int t = 0; t < TDIM; t++) {
        const float* row = syms + ((size_t)t * NTOK + warp) * DSYM;
        float s = 0.f;
#pragma unroll
        for (int i = 0; i < 8; i++) s += row[lane + 32 * i] * wq[i];
#pragma unroll
        for (int o = 16; o; o >>= 1) s += __shfl_xor_sync(0xffffffffu, s, o);
        if (s > best) { best = s; bt = t; }   // strict >  => first max (JAX argmax)
    }
    if (lane == 0) {
        g_top[warp] = bt;
        g_used[bt] = 1;                       // all writers store 1; race benign
    }
}

__global__ void k_cbnorm(const float* __restrict__ cb) {
    int c = blockIdx.x * blockDim.x + threadIdx.x;
    if (c < NCODE) {
        float s = 0.f;
        const float* row = cb + (size_t)c * DSYM;
#pragma unroll 8
        for (int k = 0; k < DSYM; k++) { float v = row[k]; s += v * v; }
        g_cbn[c] = s;
    }
}

// one warp per token: argmin_c (||cb_c||^2 - 2*dot)  + gather quantized row
__global__ void k_vq(const float* __restrict__ cb,
                     float* __restrict__ quant_out,
                     float* __restrict__ idx_out) {
    int warp = (blockIdx.x * blockDim.x + threadIdx.x) >> 5;
    int lane = threadIdx.x & 31;
    if (warp >= NTOK) return;
    const float* srow = g_scores + (size_t)warp * NCODE;
    float best = 3.0e38f;
    int bi = 0x7fffffff;
    for (int c = lane; c < NCODE; c += 32) {
        float d = g_cbn[c] - 2.f * srow[c];
        if (d < best) { best = d; bi = c; }   // ascending scan keeps lowest idx
    }
#pragma unroll
    for (int o = 16; o; o >>= 1) {
        float ov = __shfl_xor_sync(0xffffffffu, best, o);
        int   oi = __shfl_xor_sync(0xffffffffu, bi, o);
        if (ov < best || (ov == best && oi < bi)) { best = ov; bi = oi; }
    }
    // bi identical across warp
    const float4* q = (const float4*)(cb + (size_t)bi * DSYM);
    float4* dst = (float4*)(quant_out + (size_t)warp * DSYM);
#pragma unroll
    for (int i = lane; i < DSYM / 4; i += 32) dst[i] = q[i];
    if (lane == 0) idx_out[warp] = (float)bi;
}

__global__ void k_mask(float* __restrict__ mask_out) {
    int t = threadIdx.x;
    if (t < TDIM) mask_out[t] = (g_used[t] == 0) ? 1.f : 0.f;
}

// ---------------- tiled fp32 SGEMM ------------------------------------------
// C[M,N] = A[M,K] @ B[K,N] (+bias) (relu?) (+res)
// AMODE 0: A0 row-major [M,K]
// AMODE 1: "zcat+gather": k<split -> A0[m, k] (ld=split)
//                         else    -> A1[(top[m]*NTOK + m)*(K-split) + (k-split)]
// AMODE 2: "hcat": k<split -> A0[m,k] (ld=split); else A1[m, k-split] (ld=K-split)
// BMODE 0: B row-major [K,N];  BMODE 1: B is [N,K], element(k,n)=B[n*K+k]
#define BM 128
#define BN 128
#define BK 16
#define TM 8
#define TN 8

template <int AMODE, int BMODE>
__global__ __launch_bounds__(256)
void k_sgemm(const float* __restrict__ A0, const float* __restrict__ A1,
             const int* __restrict__ top,
             const float* __restrict__ B,
             const float* __restrict__ bias,
             const float* __restrict__ res,
             int relu,
             float* __restrict__ C,
             int M, int N, int K, int split)
{
    __shared__ float As[BK][BM + 4];
    __shared__ float Bs[BK][BN + 4];
    const int bm = blockIdx.y * BM;
    const int bn = blockIdx.x * BN;
    const int tid = threadIdx.x;
    const int tx = tid & 15;       // n dir
    const int ty = tid >> 4;       // m dir

    // hoist per-thread A row bases (row fixed across k tiles)
    const float* a0base[2];
    const float* a1base[2];
    int kcof[2];
#pragma unroll
    for (int l = 0; l < 2; l++) {
        int c = tid + l * 256;
        int row = c >> 2;                 // 0..127
        kcof[l] = (c & 3) * 4;            // 0,4,8,12
        int gm = bm + row;
        if (AMODE == 0) {
            a0base[l] = A0 + (size_t)gm * K;
            a1base[l] = nullptr;
        } else if (AMODE == 1) {
            a0base[l] = A0 + (size_t)gm * split;
            a1base[l] = A1 + ((size_t)top[gm] * NTOK + gm) * (size_t)(K - split);
        } else {
            a0base[l] = A0 + (size_t)gm * split;
            a1base[l] = A1 + (size_t)gm * (K - split);
        }
    }

    float acc[TM][TN] = {};
    for (int kt = 0; kt < K; kt += BK) {
        // ---- load A tile (transposed into As) ----
#pragma unroll
        for (int l = 0; l < 2; l++) {
            int c = tid + l * 256;
            int row = c >> 2;
            int kc = kcof[l];
            int gk = kt + kc;
            const float* src;
            if (AMODE == 0) src = a0base[l] + gk;
            else src = (gk < split) ? (a0base[l] + gk) : (a1base[l] + (gk - split));
            float4 v = *(const float4*)src;
            As[kc + 0][row] = v.x;
            As[kc + 1][row] = v.y;
            As[kc + 2][row] = v.z;
            As[kc + 3][row] = v.w;
        }
        // ---- load B tile ----
#pragma unroll
        for (int l = 0; l < 2; l++) {
            int c = tid + l * 256;
            if (BMODE == 0) {
                int row = c >> 5;          // k within tile
                int nc = (c & 31) * 4;
                float4 v = *(const float4*)(B + (size_t)(kt + row) * N + bn + nc);
                *(float4*)&Bs[row][nc] = v;
            } else {
                int n = c >> 2;            // 0..127
                int kc = (c & 3) * 4;
                float4 v = *(const float4*)(B + (size_t)(bn + n) * K + kt + kc);
                Bs[kc + 0][n] = v.x;
                Bs[kc + 1][n] = v.y;
                Bs[kc + 2][n] = v.z;
                Bs[kc + 3][n] = v.w;
            }
        }
        __syncthreads();
#pragma unroll
        for (int k = 0; k < BK; k++) {
            float a[TM], b[TN];
#pragma unroll
            for (int i = 0; i < TM; i++) a[i] = As[k][ty * TM + i];
#pragma unroll
            for (int j = 0; j < TN; j++) b[j] = Bs[k][tx * TN + j];
#pragma unroll
            for (int i = 0; i < TM; i++)
#pragma unroll
                for (int j = 0; j < TN; j++)
                    acc[i][j] += a[i] * b[j];
        }
        __syncthreads();
    }
    // ---- epilogue ----
#pragma unroll
    for (int i = 0; i < TM; i++) {
        int gm = bm + ty * TM + i;
#pragma unroll
        for (int j = 0; j < TN; j++) {
            int gn = bn + tx * TN + j;
            float v = acc[i][j];
            if (bias) v += bias[gn];
            if (relu) v = fmaxf(v, 0.f);
            if (res)  v += res[(size_t)gm * N + gn];
            C[(size_t)gm * N + gn] = v;
        }
    }
}

// ---------------- launch ----------------------------------------------------
extern "C" void kernel_launch(void* const* d_in, const int* in_sizes, int n_in,
                              void* d_out, int out_size)
{
    const float* token = (const float*)d_in[0];
    const float* syms  = (const float*)d_in[1];
    const float* outs  = (const float*)d_in[3];
    const float* Wq    = (const float*)d_in[5];
    const float* Wread = (const float*)d_in[7];
    const float* bread = (const float*)d_in[8];
    const float* Wsym  = (const float*)d_in[9];
    const float* bsym  = (const float*)d_in[10];
    const float* Wc1   = (const float*)d_in[11];
    const float* bc1   = (const float*)d_in[12];
    const float* Wc2   = (const float*)d_in[13];
    const float* bc2   = (const float*)d_in[14];
    const float* cb    = (const float*)d_in[15];

    float* out        = (float*)d_out;
    float* out_node   = out;                                  // 8192*1024
    float* out_quant  = out + (size_t)NTOK * DLAT;            // 8192*256
    float* out_idx    = out_quant + (size_t)NTOK * DSYM;      // 8192
    float* out_mask   = out_idx + NTOK;                       // 8

    void *p_top, *p_zread, *p_raw, *p_scores, *p_h;
    cudaGetSymbolAddress(&p_top,    g_top);
    cudaGetSymbolAddress(&p_zread,  g_zread);
    cudaGetSymbolAddress(&p_raw,    g_raw);
    cudaGetSymbolAddress(&p_scores, g_scores);
    cudaGetSymbolAddress(&p_h,      g_h);
    int*   top    = (int*)p_top;
    float* zread  = (float*)p_zread;
    float* raw    = (float*)p_raw;
    float* scores = (float*)p_scores;
    float* h      = (float*)p_h;

    k_init_used<<<1, 32>>>();
    k_topidx<<<(NTOK * 32 + 255) / 256, 256>>>(syms, Wq);
    k_cbnorm<<<2, 256>>>(cb);

    // z_read = [token | gathered_bus] @ Wread + bread    (M=8192,K=2048,N=1024)
    {
        dim3 grid(DLAT / BN, NTOK / BM);
        k_sgemm<1, 0><<<grid, 256>>>(token, outs, top, Wread, bread, nullptr, 0,
                                     zread, NTOK, DLAT, 2 * DLAT, DLAT);
    }
    // raw_symbol = z_read @ Wsym + bsym                  (K=1024,N=256)
    {
        dim3 grid(DSYM / BN, NTOK / BM);
        k_sgemm<0, 0><<<grid, 256>>>(zread, nullptr, nullptr, Wsym, bsym, nullptr, 0,
                                     raw, NTOK, DSYM, DLAT, 0);
    }
    // scores = raw @ codebook^T                          (K=256,N=512, B transposed)
    {
        dim3 grid(NCODE / BN, NTOK / BM);
        k_sgemm<0, 1><<<grid, 256>>>(raw, nullptr, nullptr, cb, nullptr, nullptr, 0,
                                     scores, NTOK, NCODE, DSYM, 0);
    }
    // VQ argmin + quantized gather + indices
    k_vq<<<(NTOK * 32 + 255) / 256, 256>>>(cb, out_quant, out_idx);

    // h = relu([z_read | quantized] @ Wc1 + bc1)         (K=1280,N=1024)
    {
        dim3 grid(DLAT / BN, NTOK / BM);
        k_sgemm<2, 0><<<grid, 256>>>(zread, out_quant, nullptr, Wc1, bc1, nullptr, 1,
                                     h, NTOK, DLAT, DLAT + DSYM, DLAT);
    }
    // node_output = h @ Wc2 + bc2 + token_state          (K=1024,N=1024)
    {
        dim3 grid(DLAT / BN, NTOK / BM);
        k_sgemm<0, 0><<<grid, 256>>>(h, nullptr, nullptr, Wc2, bc2, token, 0,
                                     out_node, NTOK, DLAT, DLAT, 0);
    }
    k_mask<<<1, 32>>>(out_mask);
}

// round 2
// speedup vs baseline: 1.1042x; 1.1042x over previous
#include <cuda_runtime.h>

#define TDIM   8
#define NTOK   8192      // B*S = 4*2048
#define DLAT   1024
#define DSYM   256
#define NCODE  512

// ---------------- scratch (static device globals; no runtime allocation) ----
static __device__ int   g_top[NTOK];
static __device__ int   g_used[TDIM];
static __device__ float g_zread[NTOK * DLAT];     // 32 MB
static __device__ float g_raw[NTOK * DSYM];       //  8 MB
static __device__ float g_scores[NTOK * NCODE];   // 16 MB
static __device__ float g_h[NTOK * DLAT];         // 32 MB
static __device__ float g_cbn[NCODE];

// ---------------- small kernels --------------------------------------------
__global__ void k_init_used() {
    if (threadIdx.x < TDIM) g_used[threadIdx.x] = 0;
}

// one warp per token: relevance[t] = dot(syms[t][n], Wq); argmax over t
__global__ void k_topidx(const float* __restrict__ syms,
                         const float* __restrict__ Wq) {
    int warp = (blockIdx.x * blockDim.x + threadIdx.x) >> 5;
    int lane = threadIdx.x & 31;
    if (warp >= NTOK) return;
    float wq[8];
#pragma unroll
    for (int i = 0; i < 8; i++) wq[i] = Wq[lane + 32 * i];
    float best = -3.0e38f;
    int bt = 0;
    for (int t = 0; t < TDIM; t++) {
        const float* row = syms + ((size_t)t * NTOK + warp) * DSYM;
        float s = 0.f;
#pragma unroll
        for (int i = 0; i < 8; i++) s += row[lane + 32 * i] * wq[i];
#pragma unroll
        for (int o = 16; o; o >>= 1) s += __shfl_xor_sync(0xffffffffu, s, o);
        if (s > best) { best = s; bt = t; }   // strict >  => first max (JAX argmax)
    }
    if (lane == 0) {
        g_top[warp] = bt;
        g_used[bt] = 1;                       // all writers store 1; race benign
    }
}

__global__ void k_cbnorm(const float* __restrict__ cb) {
    int c = blockIdx.x * blockDim.x + threadIdx.x;
    if (c < NCODE) {
        float s = 0.f;
        const float* row = cb + (size_t)c * DSYM;
#pragma unroll 8
        for (int k = 0; k < DSYM; k++) { float v = row[k]; s += v * v; }
        g_cbn[c] = s;
    }
}

// one warp per token: argmin_c (||cb_c||^2 - 2*dot)  + gather quantized row
__global__ void k_vq(const float* __restrict__ cb,
                     float* __restrict__ quant_out,
                     float* __restrict__ idx_out) {
    int warp = (blockIdx.x * blockDim.x + threadIdx.x) >> 5;
    int lane = threadIdx.x & 31;
    if (warp >= NTOK) return;
    const float* srow = g_scores + (size_t)warp * NCODE;
    float best = 3.0e38f;
    int bi = 0x7fffffff;
    for (int c = lane; c < NCODE; c += 32) {
        float d = g_cbn[c] - 2.f * srow[c];
        if (d < best) { best = d; bi = c; }   // ascending scan keeps lowest idx
    }
#pragma unroll
    for (int o = 16; o; o >>= 1) {
        float ov = __shfl_xor_sync(0xffffffffu, best, o);
        int   oi = __shfl_xor_sync(0xffffffffu, bi, o);
        if (ov < best || (ov == best && oi < bi)) { best = ov; bi = oi; }
    }
    // bi identical across warp
    const float4* q = (const float4*)(cb + (size_t)bi * DSYM);
    float4* dst = (float4*)(quant_out + (size_t)warp * DSYM);
#pragma unroll
    for (int i = lane; i < DSYM / 4; i += 32) dst[i] = q[i];
    if (lane == 0) idx_out[warp] = (float)bi;
}

__global__ void k_mask(float* __restrict__ mask_out) {
    int t = threadIdx.x;
    if (t < TDIM) mask_out[t] = (g_used[t] == 0) ? 1.f : 0.f;
}

// ---------------- tiled fp32 SGEMM (double-buffered, float4 LDS) ------------
// C[M,N] = A[M,K] @ B[K,N] (+bias) (relu?) (+res)
// AMODE 0: A0 row-major [M,K]
// AMODE 1: "zcat+gather": k<split -> A0[m, k] (ld=split)
//                         else    -> A1[(top[m]*NTOK + m)*(K-split) + (k-split)]
// AMODE 2: "hcat": k<split -> A0[m,k] (ld=split); else A1[m, k-split] (ld=K-split)
// BMODE 0: B row-major [K,N];  BMODE 1: B is [N,K], element(k,n)=B[n*K+k]
#define BM 128
#define BN 128
#define BK 16
#define TM 8
#define TN 8

template <int AMODE, int BMODE>
__global__ __launch_bounds__(256, 2)
void k_sgemm(const float* __restrict__ A0, const float* __restrict__ A1,
             const int* __restrict__ top,
             const float* __restrict__ B,
             const float* __restrict__ bias,
             const float* __restrict__ res,
             int relu,
             float* __restrict__ C,
             int M, int N, int K, int split)
{
    __shared__ float As[2][BK][BM + 4];
    __shared__ float Bs[2][BK][BN + 4];
    const int bm = blockIdx.y * BM;
    const int bn = blockIdx.x * BN;
    const int tid = threadIdx.x;
    const int tx = tid & 15;       // n dir
    const int ty = tid >> 4;       // m dir

    // per-thread A load coords (row fixed across k tiles)
    const float* a0base[2];
    const float* a1base[2];
    int arow[2], akc[2];
#pragma unroll
    for (int l = 0; l < 2; l++) {
        int c = tid + l * 256;
        arow[l] = c >> 2;                 // 0..127
        akc[l]  = (c & 3) * 4;            // 0,4,8,12
        int gm = bm + arow[l];
        if (AMODE == 0) {
            a0base[l] = A0 + (size_t)gm * K;
            a1base[l] = nullptr;
        } else if (AMODE == 1) {
            a0base[l] = A0 + (size_t)gm * split;
            a1base[l] = A1 + ((size_t)top[gm] * NTOK + gm) * (size_t)(K - split);
        } else {
            a0base[l] = A0 + (size_t)gm * split;
            a1base[l] = A1 + (size_t)gm * (K - split);
        }
    }

    float4 pa[2], pb[2];

    // ---- tile loaders (global -> registers) ----
    auto load_tile = [&](int kt) {
#pragma unroll
        for (int l = 0; l < 2; l++) {
            int gk = kt + akc[l];
            const float* src;
            if (AMODE == 0) src = a0base[l] + gk;
            else src = (gk < split) ? (a0base[l] + gk) : (a1base[l] + (gk - split));
            pa[l] = *(const float4*)src;
        }
#pragma unroll
        for (int l = 0; l < 2; l++) {
            int c = tid + l * 256;
            if (BMODE == 0) {
                int row = c >> 5;          // k within tile
                int nc = (c & 31) * 4;
                pb[l] = *(const float4*)(B + (size_t)(kt + row) * N + bn + nc);
            } else {
                int n = c >> 2;            // 0..127
                int kc = (c & 3) * 4;
                pb[l] = *(const float4*)(B + (size_t)(bn + n) * K + kt + kc);
            }
        }
    };
    auto store_tile = [&](int buf) {
#pragma unroll
        for (int l = 0; l < 2; l++) {
            int row = arow[l], kc = akc[l];
            As[buf][kc + 0][row] = pa[l].x;
            As[buf][kc + 1][row] = pa[l].y;
            As[buf][kc + 2][row] = pa[l].z;
            As[buf][kc + 3][row] = pa[l].w;
        }
#pragma unroll
        for (int l = 0; l < 2; l++) {
            int c = tid + l * 256;
            if (BMODE == 0) {
                int row = c >> 5;
                int nc = (c & 31) * 4;
                *(float4*)&Bs[buf][row][nc] = pb[l];
            } else {
                int n = c >> 2;
                int kc = (c & 3) * 4;
                Bs[buf][kc + 0][n] = pb[l].x;
                Bs[buf][kc + 1][n] = pb[l].y;
                Bs[buf][kc + 2][n] = pb[l].z;
                Bs[buf][kc + 3][n] = pb[l].w;
            }
        }
    };

    float acc[TM][TN] = {};
    const int ktiles = K / BK;
    int buf = 0;

    load_tile(0);
    store_tile(0);
    __syncthreads();

    for (int t = 0; t < ktiles; t++) {
        const bool more = (t + 1 < ktiles);
        if (more) load_tile((t + 1) * BK);

#pragma unroll
        for (int k = 0; k < BK; k++) {
            float4 a0 = *(const float4*)&As[buf][k][ty * TM];
            float4 a1 = *(const float4*)&As[buf][k][ty * TM + 4];
            float4 b0 = *(const float4*)&Bs[buf][k][tx * TN];
            float4 b1 = *(const float4*)&Bs[buf][k][tx * TN + 4];
            float a[TM] = {a0.x, a0.y, a0.z, a0.w, a1.x, a1.y, a1.z, a1.w};
            float b[TN] = {b0.x, b0.y, b0.z, b0.w, b1.x, b1.y, b1.z, b1.w};
#pragma unroll
            for (int i = 0; i < TM; i++)
#pragma unroll
                for (int j = 0; j < TN; j++)
                    acc[i][j] += a[i] * b[j];
        }

        if (more) {
            store_tile(buf ^ 1);
            __syncthreads();
            buf ^= 1;
        }
    }

    // ---- epilogue (vectorized) ----
    float4 bv0, bv1;
    if (bias) {
        bv0 = *(const float4*)(bias + bn + tx * TN);
        bv1 = *(const float4*)(bias + bn + tx * TN + 4);
    } else {
        bv0 = make_float4(0.f, 0.f, 0.f, 0.f);
        bv1 = bv0;
    }
#pragma unroll
    for (int i = 0; i < TM; i++) {
        int gm = bm + ty * TM + i;
        size_t base = (size_t)gm * N + bn + tx * TN;
        float4 v0 = make_float4(acc[i][0] + bv0.x, acc[i][1] + bv0.y,
                                acc[i][2] + bv0.z, acc[i][3] + bv0.w);
        float4 v1 = make_float4(acc[i][4] + bv1.x, acc[i][5] + bv1.y,
                                acc[i][6] + bv1.z, acc[i][7] + bv1.w);
        if (relu) {
            v0.x = fmaxf(v0.x, 0.f); v0.y = fmaxf(v0.y, 0.f);
            v0.z = fmaxf(v0.z, 0.f); v0.w = fmaxf(v0.w, 0.f);
            v1.x = fmaxf(v1.x, 0.f); v1.y = fmaxf(v1.y, 0.f);
            v1.z = fmaxf(v1.z, 0.f); v1.w = fmaxf(v1.w, 0.f);
        }
        if (res) {
            float4 r0 = *(const float4*)(res + base);
            float4 r1 = *(const float4*)(res + base + 4);
            v0.x += r0.x; v0.y += r0.y; v0.z += r0.z; v0.w += r0.w;
            v1.x += r1.x; v1.y += r1.y; v1.z += r1.z; v1.w += r1.w;
        }
        *(float4*)(C + base)     = v0;
        *(float4*)(C + base + 4) = v1;
    }
}

// ---------------- launch ----------------------------------------------------
extern "C" void kernel_launch(void* const* d_in, const int* in_sizes, int n_in,
                              void* d_out, int out_size)
{
    const float* token = (const float*)d_in[0];
    const float* syms  = (const float*)d_in[1];
    const float* outs  = (const float*)d_in[3];
    const float* Wq    = (const float*)d_in[5];
    const float* Wread = (const float*)d_in[7];
    const float* bread = (const float*)d_in[8];
    const float* Wsym  = (const float*)d_in[9];
    const float* bsym  = (const float*)d_in[10];
    const float* Wc1   = (const float*)d_in[11];
    const float* bc1   = (const float*)d_in[12];
    const float* Wc2   = (const float*)d_in[13];
    const float* bc2   = (const float*)d_in[14];
    const float* cb    = (const float*)d_in[15];

    float* out        = (float*)d_out;
    float* out_node   = out;                                  // 8192*1024
    float* out_quant  = out + (size_t)NTOK * DLAT;            // 8192*256
    float* out_idx    = out_quant + (size_t)NTOK * DSYM;      // 8192
    float* out_mask   = out_idx + NTOK;                       // 8

    void *p_top, *p_zread, *p_raw, *p_scores, *p_h;
    cudaGetSymbolAddress(&p_top,    g_top);
    cudaGetSymbolAddress(&p_zread,  g_zread);
    cudaGetSymbolAddress(&p_raw,    g_raw);
    cudaGetSymbolAddress(&p_scores, g_scores);
    cudaGetSymbolAddress(&p_h,      g_h);
    int*   top    = (int*)p_top;
    float* zread  = (float*)p_zread;
    float* raw    = (float*)p_raw;
    float* scores = (float*)p_scores;
    float* h      = (float*)p_h;

    k_init_used<<<1, 32>>>();
    k_topidx<<<(NTOK * 32 + 255) / 256, 256>>>(syms, Wq);
    k_cbnorm<<<2, 256>>>(cb);

    // z_read = [token | gathered_bus] @ Wread + bread    (M=8192,K=2048,N=1024)
    {
        dim3 grid(DLAT / BN, NTOK / BM);
        k_sgemm<1, 0><<<grid, 256>>>(token, outs, top, Wread, bread, nullptr, 0,
                                     zread, NTOK, DLAT, 2 * DLAT, DLAT);
    }
    // raw_symbol = z_read @ Wsym + bsym                  (K=1024,N=256)
    {
        dim3 grid(DSYM / BN, NTOK / BM);
        k_sgemm<0, 0><<<grid, 256>>>(zread, nullptr, nullptr, Wsym, bsym, nullptr, 0,
                                     raw, NTOK, DSYM, DLAT, 0);
    }
    // scores = raw @ codebook^T                          (K=256,N=512, B transposed)
    {
        dim3 grid(NCODE / BN, NTOK / BM);
        k_sgemm<0, 1><<<grid, 256>>>(raw, nullptr, nullptr, cb, nullptr, nullptr, 0,
                                     scores, NTOK, NCODE, DSYM, 0);
    }
    // VQ argmin + quantized gather + indices
    k_vq<<<(NTOK * 32 + 255) / 256, 256>>>(cb, out_quant, out_idx);

    // h = relu([z_read | quantized] @ Wc1 + bc1)         (K=1280,N=1024)
    {
        dim3 grid(DLAT / BN, NTOK / BM);
        k_sgemm<2, 0><<<grid, 256>>>(zread, out_quant, nullptr, Wc1, bc1, nullptr, 1,
                                     h, NTOK, DLAT, DLAT + DSYM, DLAT);
    }
    // node_output = h @ Wc2 + bc2 + token_state          (K=1024,N=1024)
    {
        dim3 grid(DLAT / BN, NTOK / BM);
        k_sgemm<0, 0><<<grid, 256>>>(h, nullptr, nullptr, Wc2, bc2, token, 0,
                                     out_node, NTOK, DLAT, DLAT, 0);
    }
    k_mask<<<1, 32>>>(out_mask);
}